// round 1
// baseline (speedup 1.0000x reference)
#include <cuda_runtime.h>

// RandomShiftsAug: out[n,c,j,i] = x[n, c, src_h(n,j), src_w(n,i)]
//   kx = shift[n,0], ky = shift[n,1]  (both in [0, 8])
//   th    = max(ky + j - 4, 0)            (<= 87, so only lower clamp binds)
//   src_h = th - 84*(th >= 84)            (tile-by-5 wrap; only 84..87 wrap)
//   src_w = clamp(kx + i - 4, 0, 419)
//
// Shapes: x (128, 9, 84, 420) f32 ; shift (128, 2) i32 ; out (128, 9, 84, 420) f32
// Pure gather, HBM-bound: ~325 MB total traffic.

#define N_BATCH 128
#define CH      9
#define H       84
#define W       420
#define W4      (W / 4)          // 105 float4 per row
#define NVEC    (N_BATCH * CH * H * W4)   // 10,160,640
#define THREADS 256
#define BLOCKS  (NVEC / THREADS)          // 39,690 exactly

__global__ __launch_bounds__(THREADS)
void rand_shift_kernel(const float* __restrict__ x,
                       const int*   __restrict__ shift,
                       float4*      __restrict__ out)
{
    const int idx = blockIdx.x * THREADS + threadIdx.x;   // < NVEC, exact grid

    // Decompose: idx = ((nc*84 + j)*105 + i4)
    const int i4 = idx % W4;
    const int r  = idx / W4;
    const int j  = r % H;
    const int nc = r / H;              // n*9 + c
    const int n  = nc / CH;

    const int kx = __ldg(&shift[2 * n]);
    const int ky = __ldg(&shift[2 * n + 1]);

    // Row mapping
    int th = ky + j - 4;
    th = th < 0 ? 0 : th;
    const int src_h = (th >= H) ? (th - H) : th;

    const float* __restrict__ row = x + (nc * H + src_h) * W;

    // Column mapping: 4 consecutive source cols, clamped to [0, 419]
    const int base = kx + 4 * i4 - 4;
    const int w0 = min(max(base,     0), W - 1);
    const int w1 = min(max(base + 1, 0), W - 1);
    const int w2 = min(max(base + 2, 0), W - 1);
    const int w3 = min(max(base + 3, 0), W - 1);

    float4 v;
    v.x = __ldg(row + w0);
    v.y = __ldg(row + w1);
    v.z = __ldg(row + w2);
    v.w = __ldg(row + w3);

    out[idx] = v;
}

extern "C" void kernel_launch(void* const* d_in, const int* in_sizes, int n_in,
                              void* d_out, int out_size)
{
    const float* x     = (const float*)d_in[0];
    const int*   shift = (const int*)d_in[1];
    float4*      out   = (float4*)d_out;

    rand_shift_kernel<<<BLOCKS, THREADS>>>(x, shift, out);
}

// round 2
// speedup vs baseline: 1.0846x; 1.0846x over previous
#include <cuda_runtime.h>

// RandomShiftsAug: out[n,c,j,i] = x[n, c, src_h(n,j), src_w(n,i)]
//   kx = shift[n,0], ky = shift[n,1]  (both in [0, 8])
//   th    = max(ky + j - 4, 0)            (<= 87, only lower clamp binds)
//   src_h = th - 84*(th >= 84)            (tile-by-5 wrap; only 84..87 wrap)
//   src_w = clamp(kx + i - 4, 0, 419)
//
// HBM-bound gather (~325 MB). This version: each thread produces 4 output
// float4 vectors at the same i4 across 4 consecutive rows j. Column clamps
// are row-invariant -> computed once; 16 independent LDG.32 in flight
// (MLP=16) before the 4 coalesced STG.128.

#define N_BATCH 128
#define CH      9
#define H       84
#define W       420
#define W4      (W / 4)               // 105 float4 per row
#define JG      (H / 4)               // 21 row-groups of 4
#define NWORK   (N_BATCH * CH * JG * W4)   // 2,540,160 threads
#define THREADS 256
#define BLOCKS  ((NWORK + THREADS - 1) / THREADS)   // 9923

__global__ __launch_bounds__(THREADS)
void rand_shift_kernel(const float* __restrict__ x,
                       const int*   __restrict__ shift,
                       float4*      __restrict__ out)
{
    const int idx = blockIdx.x * THREADS + threadIdx.x;
    if (idx >= NWORK) return;

    // idx = ((nc*21 + jg)*105 + i4)
    const int i4 = idx % W4;
    const int r  = idx / W4;
    const int jg = r % JG;
    const int nc = r / JG;            // n*9 + c
    const int n  = nc / CH;

    const int kx = __ldg(&shift[2 * n]);
    const int ky = __ldg(&shift[2 * n + 1]);

    // Column mapping: identical for all 4 rows of this thread.
    const int base = kx + 4 * i4 - 4;
    const int w0 = min(max(base,     0), W - 1);
    const int w1 = min(max(base + 1, 0), W - 1);
    const int w2 = min(max(base + 2, 0), W - 1);
    const int w3 = min(max(base + 3, 0), W - 1);

    const int j0 = 4 * jg;

    // Row pointers for the 4 consecutive output rows.
    const float* rowp[4];
#pragma unroll
    for (int jj = 0; jj < 4; jj++) {
        int th = ky + (j0 + jj) - 4;
        th = th < 0 ? 0 : th;
        const int src_h = (th >= H) ? (th - H) : th;
        rowp[jj] = x + (nc * H + src_h) * W;
    }

    // 16 independent loads, front-batched.
    float4 v[4];
#pragma unroll
    for (int jj = 0; jj < 4; jj++) {
        v[jj].x = __ldg(rowp[jj] + w0);
        v[jj].y = __ldg(rowp[jj] + w1);
        v[jj].z = __ldg(rowp[jj] + w2);
        v[jj].w = __ldg(rowp[jj] + w3);
    }

    // 4 coalesced stores (warp covers 32 consecutive i4 at the same row).
    float4* outp = out + (nc * H + j0) * W4 + i4;
#pragma unroll
    for (int jj = 0; jj < 4; jj++) {
        outp[jj * W4] = v[jj];
    }
}

extern "C" void kernel_launch(void* const* d_in, const int* in_sizes, int n_in,
                              void* d_out, int out_size)
{
    const float* x     = (const float*)d_in[0];
    const int*   shift = (const int*)d_in[1];
    float4*      out   = (float4*)d_out;

    rand_shift_kernel<<<BLOCKS, THREADS>>>(x, shift, out);
}